// round 15
// baseline (speedup 1.0000x reference)
#include <cuda_runtime.h>
#include <math.h>

#define NB 16384
#define ND 16
#define KNN 25
#define LAMBDA_TSA 0.1f
#define FULLM 0xffffffffu
#define FLTMAX 3.402823466e+38f
#define ENCMAX 0xFF7FFFFFu   // fenc(FLTMAX)

#define NSPLIT 2
#define CHALF (NB / NSPLIT)          // 8192 candidates per split
#define QW 16                        // queries per warp (MMA m16)
#define WPB 4                        // warps per block
#define CT 128                       // candidates per smem tile
#define CROW 20                      // u32 stride per candidate row (80B)

// ---------------- device scratch (no allocations allowed) ----------------
__device__ float    g_sq[NB];
__device__ unsigned g_cpack[NB * 16];        // per cand: 8 dim-pairs x (hi2,lo2)
__device__ unsigned g_pe[NSPLIT][NB][KNN];   // partial top-25 (encoded dist)
__device__ int      g_pi[NSPLIT][NB][KNN];   // partial top-25 (indices)
__device__ int      g_nbrs[NB][KNN];
__device__ float    g_acc_recon;
__device__ float    g_acc_tsa;

// monotone float<->uint encode (order-preserving)
__device__ __forceinline__ unsigned fenc(float f) {
    int b = __float_as_int(f);
    return (b >= 0) ? ((unsigned)b | 0x80000000u) : ~(unsigned)b;
}
__device__ __forceinline__ float fdec(unsigned u) {
    int b = (u & 0x80000000u) ? (int)(u & 0x7fffffffu) : (int)~u;
    return __int_as_float(b);
}
// fp32 -> bf16 bits (round-to-nearest-even)
__device__ __forceinline__ unsigned f2bf(float x) {
    unsigned u = __float_as_uint(x);
    return (u + 0x7fffu + ((u >> 16) & 1u)) >> 16;
}
__device__ __forceinline__ float bf2f(unsigned b) { return __uint_as_float(b << 16); }

#define MMA16816(c0,c1,c2,c3,a0,a1,a2,a3,b0,b1) \
    asm("mma.sync.aligned.m16n8k16.row.col.f32.bf16.bf16.f32 " \
        "{%0,%1,%2,%3},{%4,%5,%6,%7},{%8,%9},{%0,%1,%2,%3};" \
        : "+f"(c0),"+f"(c1),"+f"(c2),"+f"(c3) \
        : "r"(a0),"r"(a1),"r"(a2),"r"(a3),"r"(b0),"r"(b1))

// ---------------- kernel 1: squared norms + zero accumulators ----------------
__global__ void k_setup(const float* __restrict__ raw) {
    int i = blockIdx.x * blockDim.x + threadIdx.x;
    if (i < NB) {
        const float4* r4 = reinterpret_cast<const float4*>(raw + (size_t)i * ND);
        float s = 0.f;
#pragma unroll
        for (int j = 0; j < 4; ++j) {
            float4 v = r4[j];
            s = fmaf(v.x, v.x, s); s = fmaf(v.y, v.y, s);
            s = fmaf(v.z, v.z, s); s = fmaf(v.w, v.w, s);
        }
        g_sq[i] = s;
    }
    if (i == 0) { g_acc_recon = 0.f; g_acc_tsa = 0.f; }
}

// ---------------- kernel 2: recon MSE sum ----------------
__global__ void k_recon(const float* __restrict__ o, const float* __restrict__ t) {
    const float4* o4 = reinterpret_cast<const float4*>(o);
    const float4* t4 = reinterpret_cast<const float4*>(t);
    const int n4 = NB * ND / 4;
    float s = 0.f;
    for (int idx = blockIdx.x * blockDim.x + threadIdx.x; idx < n4;
         idx += gridDim.x * blockDim.x) {
        float4 a = o4[idx], b = t4[idx];
        float dx = a.x - b.x, dy = a.y - b.y, dz = a.z - b.z, dw = a.w - b.w;
        s = fmaf(dx, dx, s); s = fmaf(dy, dy, s);
        s = fmaf(dz, dz, s); s = fmaf(dw, dw, s);
    }
#pragma unroll
    for (int off = 16; off; off >>= 1) s += __shfl_xor_sync(FULLM, s, off);
    __shared__ float ws[8];
    int lane = threadIdx.x & 31, wid = threadIdx.x >> 5;
    if (lane == 0) ws[wid] = s;
    __syncthreads();
    if (threadIdx.x == 0) {
        float tot = 0.f;
#pragma unroll
        for (int k = 0; k < 8; ++k) tot += ws[k];
        atomicAdd(&g_acc_recon, tot);
    }
}

// ---------------- kernel 3: pack raw into split-bf16 pairs -------------------
// per cand c, dim-pair p: g_cpack[c*16 + 2p] = {hi(x0),hi(x1)},
//                         g_cpack[c*16 + 2p+1] = {lo(x0),lo(x1)}
__global__ void k_pack(const float* __restrict__ raw) {
    int i = blockIdx.x * blockDim.x + threadIdx.x;   // 0 .. NB*8-1
    if (i >= NB * 8) return;
    int c = i >> 3, p = i & 7;
    float x0 = raw[(size_t)c * ND + 2 * p];
    float x1 = raw[(size_t)c * ND + 2 * p + 1];
    unsigned h0 = f2bf(x0), h1 = f2bf(x1);
    unsigned l0 = f2bf(x0 - bf2f(h0)), l1 = f2bf(x1 - bf2f(h1));
    g_cpack[(size_t)c * 16 + 2 * p]     = h0 | (h1 << 16);
    g_cpack[(size_t)c * 16 + 2 * p + 1] = l0 | (l1 << 16);
}

// ---------------- kernel 4: MMA distance GEMM + warp top-25 ------------------
// Warp owns 16 queries (MMA rows), streams CHALF candidates (8/step via
// m16n8k16 bf16, 3 MMAs for split precision). Top-25 lists live in smem
// (one 25-slot list per query per warp), REDUX-maintained taus in registers.
__global__ void __launch_bounds__(128) k_knn(const float* __restrict__ raw) {
    __shared__ unsigned tile_s[2][CT * CROW];
    __shared__ float2   sqp_s[2][CT / 2];
    __shared__ unsigned le_s[WPB][QW][KNN];
    __shared__ int      li_s[WPB][QW][KNN];

    const int tid  = threadIdx.x;
    const int lane = tid & 31;
    const int w    = tid >> 5;
    const int gr   = lane >> 2;        // 0..7
    const int tl   = lane & 3;         // 0..3
    const int qwb  = blockIdx.x * (WPB * QW) + w * QW;
    const int y      = blockIdx.y;
    const int cstart = y * CHALF;

    // ---- A fragments (queries, hi+lo split) ----
    unsigned a0h, a1h, a2h, a3h, a0l, a1l, a2l, a3l;
    {
        int qA = qwb + gr, qB = qwb + gr + 8;
        auto mk = [&](int q, int d, unsigned& hi, unsigned& lo) {
            float x0 = raw[(size_t)q * ND + d], x1 = raw[(size_t)q * ND + d + 1];
            unsigned h0 = f2bf(x0), h1 = f2bf(x1);
            unsigned l0 = f2bf(x0 - bf2f(h0)), l1 = f2bf(x1 - bf2f(h1));
            hi = h0 | (h1 << 16); lo = l0 | (l1 << 16);
        };
        mk(qA, 2 * tl,     a0h, a0l);
        mk(qB, 2 * tl,     a1h, a1l);
        mk(qA, 2 * tl + 8, a2h, a2l);
        mk(qB, 2 * tl + 8, a3h, a3l);
    }

    // ---- init lists ----
    for (int s = lane; s < QW * KNN; s += 32) {
        le_s[w][s / KNN][s % KNN] = ENCMAX;
        li_s[w][s / KNN][s % KNN] = 0;
    }
    float tau0f = FLTMAX, tau1f = FLTMAX;   // taus for rows gr and gr+8
    __syncwarp();

    // ---- tile fill plumbing (4 chunks of 16B per thread per tile) ----
    const uint4* cp4 = reinterpret_cast<const uint4*>(g_cpack);
    const float2* sq2 = reinterpret_cast<const float2*>(g_sq);
    uint4 pf[4]; float2 psq;
    {
        const int B0 = cstart;
#pragma unroll
        for (int k = 0; k < 4; ++k) {
            int ch = tid + k * 128, cd = ch >> 2, j = ch & 3;
            pf[k] = cp4[(size_t)(B0 + cd) * 4 + j];
        }
        if (tid < 64) psq = sq2[B0 / 2 + tid];
#pragma unroll
        for (int k = 0; k < 4; ++k) {
            int ch = tid + k * 128, cd = ch >> 2, j = ch & 3;
            *reinterpret_cast<uint4*>(&tile_s[0][cd * CROW + j * 4]) = pf[k];
        }
        if (tid < 64) sqp_s[0][tid] = psq;
    }
    __syncthreads();

    const int NT = CHALF / CT;   // 64 tiles
    for (int T = 0; T < NT; ++T) {
        const bool more = (T + 1 < NT);
        if (more) {
            const int B1 = cstart + (T + 1) * CT;
#pragma unroll
            for (int k = 0; k < 4; ++k) {
                int ch = tid + k * 128, cd = ch >> 2, j = ch & 3;
                pf[k] = cp4[(size_t)(B1 + cd) * 4 + j];
            }
            if (tid < 64) psq = sq2[B1 / 2 + tid];
        }
        const unsigned* buf = tile_s[T & 1];
        const float2*   sqb = sqp_s[T & 1];

#pragma unroll 4
        for (int step = 0; step < CT / 8; ++step) {
            // B fragments: cand = step*8 + gr, dim-pairs tl and tl+4
            const unsigned* crow = buf + (step * 8 + gr) * CROW;
            uint2 bA = *reinterpret_cast<const uint2*>(crow + tl * 2);
            uint2 bB = *reinterpret_cast<const uint2*>(crow + 8 + tl * 2);
            float2 sqv = sqb[step * 4 + tl];

            float c0 = 0.f, c1 = 0.f, c2 = 0.f, c3 = 0.f;
            MMA16816(c0, c1, c2, c3, a0h, a1h, a2h, a3h, bA.x, bB.x);  // hi*hi
            MMA16816(c0, c1, c2, c3, a0h, a1h, a2h, a3h, bA.y, bB.y);  // hi*lo
            MMA16816(c0, c1, c2, c3, a0l, a1l, a2l, a3l, bA.x, bB.x);  // lo*hi

            // epilogue: d2 = sq_c - 2*dot; lane's elems: rows {gr, gr+8},
            // cols {2tl, 2tl+1}
            float d00 = fmaf(-2.f, c0, sqv.x);
            float d01 = fmaf(-2.f, c1, sqv.y);
            float d10 = fmaf(-2.f, c2, sqv.x);
            float d11 = fmaf(-2.f, c3, sqv.y);
            bool p00 = d00 < tau0f, p01 = d01 < tau0f;
            bool p10 = d10 < tau1f, p11 = d11 < tau1f;

            unsigned rm = ((p00 | p01) ? (1u << gr) : 0u)
                        | ((p10 | p11) ? (0x100u << gr) : 0u);
            unsigned wm = __reduce_or_sync(FULLM, rm);

            while (wm) {
                int r = __ffs(wm) - 1; wm &= wm - 1;
                const bool hi8 = (r >= 8);
                const int  g   = r & 7;
                const int  qg  = qwb + r;
                float e0 = hi8 ? d10 : d00;
                float e1 = hi8 ? d11 : d01;
                bool  f0 = (gr == g) && (hi8 ? p10 : p00);
                bool  f1 = (gr == g) && (hi8 ? p11 : p01);
                int   cg0 = cstart + T * CT + step * 8 + 2 * tl;
                unsigned m0 = __ballot_sync(FULLM, f0);
                unsigned m1 = __ballot_sync(FULLM, f1);
                float tr = __shfl_sync(FULLM, hi8 ? tau1f : tau0f, g * 4);

#pragma unroll
                for (int half = 0; half < 2; ++half) {
                    unsigned m = half ? m1 : m0;
                    float    ev = half ? e1 : e0;
                    int      cv = cg0 + half;
                    while (m) {
                        int src = __ffs(m) - 1; m &= m - 1;
                        float dv = __shfl_sync(FULLM, ev, src);
                        int   ci = __shfl_sync(FULLM, cv, src);
                        if (dv < tr && ci != qg) {
                            __syncwarp();
                            unsigned mye = (lane < KNN) ? le_s[w][r][lane] : 0u;
                            unsigned mx = __reduce_max_sync(FULLM, mye);
                            int ml = __ffs(__ballot_sync(FULLM,
                                     (lane < KNN) && (mye == mx))) - 1;
                            unsigned ed = fenc(dv);
                            if (lane == ml) { le_s[w][r][lane] = ed;
                                              li_s[w][r][lane] = ci; }
                            unsigned nmx = __reduce_max_sync(FULLM,
                                (lane < KNN) ? ((lane == ml) ? ed : mye) : 0u);
                            tr = fdec(nmx);
                            if (gr == g) { if (hi8) tau1f = tr; else tau0f = tr; }
                        }
                    }
                }
            }
        }

        if (more) {
#pragma unroll
            for (int k = 0; k < 4; ++k) {
                int ch = tid + k * 128, cd = ch >> 2, j = ch & 3;
                *reinterpret_cast<uint4*>(&tile_s[(T + 1) & 1][cd * CROW + j * 4]) = pf[k];
            }
            if (tid < 64) sqp_s[(T + 1) & 1][tid] = psq;
        }
        __syncthreads();
    }

    __syncwarp();
    if (lane < KNN) {
#pragma unroll
        for (int r = 0; r < QW; ++r) {
            g_pe[y][qwb + r][lane] = le_s[w][r][lane];
            g_pi[y][qwb + r][lane] = li_s[w][r][lane];
        }
    }
}

// ---------------- kernel 5: merge the two split top-25s ----------------------
__global__ void k_merge() {
    const int lane = threadIdx.x & 31;
    const int q = blockIdx.x * 8 + (threadIdx.x >> 5);
    unsigned e  = (lane < KNN) ? g_pe[0][q][lane] : 0u;
    int      id = (lane < KNN) ? g_pi[0][q][lane] : 0;
    unsigned e2 = (lane < KNN) ? g_pe[1][q][lane] : ENCMAX;
    int      i2 = (lane < KNN) ? g_pi[1][q][lane] : 0;

    unsigned mx = __reduce_max_sync(FULLM, e);
    unsigned mask = __ballot_sync(FULLM, (lane < KNN) && (e2 < mx));
    while (mask) {
        int src = __ffs(mask) - 1; mask &= mask - 1;
        unsigned ev = __shfl_sync(FULLM, e2, src);
        int      iv = __shfl_sync(FULLM, i2, src);
        mx = __reduce_max_sync(FULLM, (lane < KNN) ? e : 0u);
        if (ev < mx) {
            int ml = __ffs(__ballot_sync(FULLM, (lane < KNN) && (e == mx))) - 1;
            if (lane == ml) { e = ev; id = iv; }
        }
    }
    if (lane < KNN) g_nbrs[q][lane] = id;
}

// ---------------- kernel 6: per-point TSA term (warp per point) --------------
// P=1: sum((Pz-Px)^2) = 2 - 2*(u.v)^2, u,v unit top-eigenvectors.
#define TSA_WPB 8
#define TSTR 20
__global__ void __launch_bounds__(256) k_tsa(const float* __restrict__ latent,
                                             const float* __restrict__ raw) {
    __shared__ float s_pts[TSA_WPB][KNN][ND];
    __shared__ float s_A[TSA_WPB][16 * TSTR];
    __shared__ float s_B[TSA_WPB][16 * TSTR];
    __shared__ float s_u[TSA_WPB][16];
    __shared__ float s_v[TSA_WPB][16];
    __shared__ float s_mu[TSA_WPB][16];
    __shared__ int   s_nb[TSA_WPB][KNN];

    const int w = threadIdx.x >> 5, lane = threadIdx.x & 31;
    const int i = blockIdx.x * TSA_WPB + w;
    const int ra   = lane >> 1;
    const int bpar = lane & 1;

    if (lane < KNN) s_nb[w][lane] = g_nbrs[i][lane];
    __syncwarp();

    for (int p = 0; p < 2; ++p) {
        const float* src = p ? raw : latent;
        float* uvec = p ? s_v[w] : s_u[w];

        for (int idx = lane; idx < KNN * ND; idx += 32) {
            int k = idx >> 4, d = idx & 15;
            s_pts[w][k][d] = src[(size_t)s_nb[w][k] * ND + d];
        }
        __syncwarp();
        if (lane < 16) {
            float m = 0.f;
#pragma unroll
            for (int k = 0; k < KNN; ++k) m += s_pts[w][k][lane];
            s_mu[w][lane] = m * (1.f / KNN);
        }
        __syncwarp();
        for (int idx = lane; idx < KNN * ND; idx += 32) {
            int k = idx >> 4, d = idx & 15;
            s_pts[w][k][d] -= s_mu[w][d];
        }
        __syncwarp();
        for (int e = lane; e < 256; e += 32) {
            int a = e >> 4, b = e & 15;
            float s = 0.f;
#pragma unroll
            for (int k = 0; k < KNN; ++k) s = fmaf(s_pts[w][k][a], s_pts[w][k][b], s);
            s_A[w][a * TSTR + b] = s;
        }
        __syncwarp();

        float* Ain = s_A[w];
        float* Aou = s_B[w];
#pragma unroll 1
        for (int sq = 0; sq < 7; ++sq) {
            const float4 A0 = *reinterpret_cast<const float4*>(Ain + ra * TSTR);
            const float4 A1 = *reinterpret_cast<const float4*>(Ain + ra * TSTR + 4);
            const float4 A2 = *reinterpret_cast<const float4*>(Ain + ra * TSTR + 8);
            const float4 A3 = *reinterpret_cast<const float4*>(Ain + ra * TSTR + 12);
#pragma unroll
            for (int ib = 0; ib < 8; ++ib) {
                const int b = bpar + 2 * ib;
                const float4 B0 = *reinterpret_cast<const float4*>(Ain + b * TSTR);
                const float4 B1 = *reinterpret_cast<const float4*>(Ain + b * TSTR + 4);
                const float4 B2 = *reinterpret_cast<const float4*>(Ain + b * TSTR + 8);
                const float4 B3 = *reinterpret_cast<const float4*>(Ain + b * TSTR + 12);
                float s = 0.f;
                s = fmaf(A0.x, B0.x, s); s = fmaf(A0.y, B0.y, s);
                s = fmaf(A0.z, B0.z, s); s = fmaf(A0.w, B0.w, s);
                s = fmaf(A1.x, B1.x, s); s = fmaf(A1.y, B1.y, s);
                s = fmaf(A1.z, B1.z, s); s = fmaf(A1.w, B1.w, s);
                s = fmaf(A2.x, B2.x, s); s = fmaf(A2.y, B2.y, s);
                s = fmaf(A2.z, B2.z, s); s = fmaf(A2.w, B2.w, s);
                s = fmaf(A3.x, B3.x, s); s = fmaf(A3.y, B3.y, s);
                s = fmaf(A3.z, B3.z, s); s = fmaf(A3.w, B3.w, s);
                Aou[ra * TSTR + b] = s;
            }
            __syncwarp();
            if (sq == 2) {
                float dv = (lane < 16) ? Aou[lane * TSTR + lane] : 0.f;
#pragma unroll
                for (int off = 16; off; off >>= 1)
                    dv = fmaxf(dv, __shfl_xor_sync(FULLM, dv, off));
                float inv = 1.f / fmaxf(dv, 1e-30f);
                for (int e = lane; e < 256; e += 32) {
                    int a = e >> 4, b = e & 15;
                    Aou[a * TSTR + b] *= inv;
                }
                __syncwarp();
            }
            float* tmp = Ain; Ain = Aou; Aou = tmp;
        }

        float bv = (lane < 16) ? Ain[lane * TSTR + lane] : -1.f;
        int   bx = (lane < 16) ? lane : 1000;
#pragma unroll
        for (int off = 16; off; off >>= 1) {
            float ov = __shfl_xor_sync(FULLM, bv, off);
            int   oi = __shfl_xor_sync(FULLM, bx, off);
            if (ov > bv || (ov == bv && oi < bx)) { bv = ov; bx = oi; }
        }
        float uv = (lane < 16) ? Ain[lane * TSTR + bx] : 0.f;
        float ss = uv * uv;
#pragma unroll
        for (int off = 16; off; off >>= 1) ss += __shfl_xor_sync(FULLM, ss, off);
        float rn = rsqrtf(ss);
        if (lane < 16) uvec[lane] = uv * rn;
        __syncwarp();
    }

    float pd = (lane < 16) ? s_u[w][lane] * s_v[w][lane] : 0.f;
#pragma unroll
    for (int off = 16; off; off >>= 1) pd += __shfl_xor_sync(FULLM, pd, off);
    if (lane == 0) {
        float term = fmaf(-2.f * pd, pd, 2.f);
        atomicAdd(&g_acc_tsa, term);
    }
}

// ---------------- kernel 7: finalize ----------------
__global__ void k_final(float* __restrict__ out) {
    out[0] = g_acc_recon * (1.f / (NB * ND)) + LAMBDA_TSA * g_acc_tsa * (1.f / NB);
}

// ---------------- launcher (kernel launches only; graph-capturable) ----------
extern "C" void kernel_launch(void* const* d_in, const int* in_sizes, int n_in,
                              void* d_out, int out_size) {
    const float* outputs = (const float*)d_in[0];
    const float* targets = (const float*)d_in[1];
    const float* latent  = (const float*)d_in[2];
    const float* raw     = (const float*)d_in[3];
    float* out = (float*)d_out;

    k_setup<<<NB / 256, 256>>>(raw);
    k_recon<<<64, 256>>>(outputs, targets);
    k_pack<<<NB * 8 / 256, 256>>>(raw);
    k_knn<<<dim3(NB / (WPB * QW), NSPLIT), 128>>>(raw);   // 4th: ncu captures it
    k_merge<<<NB / 8, 256>>>();
    k_tsa<<<NB / TSA_WPB, 256>>>(latent, raw);
    k_final<<<1, 1>>>(out);
}

// round 17
// speedup vs baseline: 1.2393x; 1.2393x over previous
#include <cuda_runtime.h>
#include <math.h>

#define NB 16384
#define ND 16
#define KNN 25
#define LAMBDA_TSA 0.1f
#define FULLM 0xffffffffu
#define FLTMAX 3.402823466e+38f

#define QPW 2                 // queries per warp
#define WPB 8                 // warps per block
#define QPB (QPW * WPB)       // 16 queries per block
#define CTILE 128             // candidates per smem tile
#define CPAD 20               // padded row stride (16 data + sq + pad); 80B

// ---------------- device scratch (no allocations allowed) ----------------
__device__ float g_sq[NB];
__device__ int   g_nbrs[NB][KNN];
__device__ float g_acc_recon;
__device__ float g_acc_tsa;

// ---------------- kernel 1: squared norms + zero accumulators ----------------
__global__ void k_setup(const float* __restrict__ raw) {
    int i = blockIdx.x * blockDim.x + threadIdx.x;
    if (i < NB) {
        const float4* r4 = reinterpret_cast<const float4*>(raw + (size_t)i * ND);
        float s = 0.f;
#pragma unroll
        for (int j = 0; j < 4; ++j) {
            float4 v = r4[j];
            s = fmaf(v.x, v.x, s); s = fmaf(v.y, v.y, s);
            s = fmaf(v.z, v.z, s); s = fmaf(v.w, v.w, s);
        }
        g_sq[i] = s;
    }
    if (i == 0) { g_acc_recon = 0.f; g_acc_tsa = 0.f; }
}

// ---------------- kernel 2: recon MSE sum ----------------
__global__ void k_recon(const float* __restrict__ o, const float* __restrict__ t) {
    const float4* o4 = reinterpret_cast<const float4*>(o);
    const float4* t4 = reinterpret_cast<const float4*>(t);
    const int n4 = NB * ND / 4;
    float s = 0.f;
    for (int idx = blockIdx.x * blockDim.x + threadIdx.x; idx < n4;
         idx += gridDim.x * blockDim.x) {
        float4 a = o4[idx], b = t4[idx];
        float dx = a.x - b.x, dy = a.y - b.y, dz = a.z - b.z, dw = a.w - b.w;
        s = fmaf(dx, dx, s); s = fmaf(dy, dy, s);
        s = fmaf(dz, dz, s); s = fmaf(dw, dw, s);
    }
#pragma unroll
    for (int off = 16; off; off >>= 1) s += __shfl_xor_sync(FULLM, s, off);
    __shared__ float ws[8];
    int lane = threadIdx.x & 31, wid = threadIdx.x >> 5;
    if (lane == 0) ws[wid] = s;
    __syncthreads();
    if (threadIdx.x == 0) {
        float tot = 0.f;
#pragma unroll
        for (int k = 0; k < 8; ++k) tot += ws[k];
        atomicAdd(&g_acc_recon, tot);
    }
}

// dummy: keeps k_knn in ncu's capture slot (4th launch)
__global__ void k_dummy() {}

// combined max+argmax over list lanes (<KNN); all lanes get the result
__device__ __forceinline__ void maxreduce25(float v, int lane, float& outv, int& outl) {
    float mv = (lane < KNN) ? v : -FLTMAX;
    int   ml = lane;
#pragma unroll
    for (int off = 16; off; off >>= 1) {
        float ov = __shfl_xor_sync(FULLM, mv, off);
        int   ol = __shfl_xor_sync(FULLM, ml, off);
        if (ov > mv || (ov == mv && ol < ml)) { mv = ov; ml = ol; }
    }
    outv = mv; outl = ml;
}

// ---------------- kernel 3: fused distance GEMM + warp-cooperative top-25 ----
// R8 form (best measured): row-major padded candidate tile (80B rows ->
// conflict-free LDS.128); single smem buffer, register prefetch across the
// two barriers. Distributed top-25 with (tau, mlane) state, seeded lists.
__global__ void __launch_bounds__(256) k_knn(const float* __restrict__ raw) {
    __shared__ float Cs[CTILE * CPAD];

    const int tid  = threadIdx.x;
    const int lane = tid & 31;
    const int w    = tid >> 5;
    const int qb   = blockIdx.x * QPB + w * QPW;
    const float4* raw4 = reinterpret_cast<const float4*>(raw);

    // per-thread tile-load coordinates (2 float4 per thread per tile)
    const int lc0 = tid >> 2,         ld0 = tid & 3;
    const int lc1 = (tid + 256) >> 2, ld1 = (tid + 256) & 3;

    float qv[QPW][ND];
#pragma unroll
    for (int j = 0; j < QPW; ++j)
#pragma unroll
        for (int d = 0; d < ND; ++d)
            qv[j][d] = __ldg(raw + (size_t)(qb + j) * ND + d);

    float lv[QPW]; int li[QPW]; float tau[QPW]; int mlane[QPW];
#pragma unroll
    for (int j = 0; j < QPW; ++j) { lv[j] = FLTMAX; li[j] = 0; tau[j] = FLTMAX; mlane[j] = 0; }

    // prefetch tile 0
    float4 pf0 = raw4[(size_t)lc0 * 4 + ld0];
    float4 pf1 = raw4[(size_t)lc1 * 4 + ld1];
    float  psq = (tid < CTILE) ? g_sq[tid] : 0.f;

    for (int t = 0; t < NB / CTILE; ++t) {
        const int cbase = t * CTILE;
        __syncthreads();   // prior tile's LDS reads complete
        *reinterpret_cast<float4*>(&Cs[lc0 * CPAD + ld0 * 4]) = pf0;
        *reinterpret_cast<float4*>(&Cs[lc1 * CPAD + ld1 * 4]) = pf1;
        if (tid < CTILE) Cs[tid * CPAD + 16] = psq;
        __syncthreads();

        if (t + 1 < NB / CTILE) {   // prefetch next tile (overlaps compute)
            const int nb4 = (cbase + CTILE) * 4;
            pf0 = raw4[(size_t)nb4 + lc0 * 4 + ld0];
            pf1 = raw4[(size_t)nb4 + lc1 * 4 + ld1];
            if (tid < CTILE) psq = g_sq[cbase + CTILE + tid];
        }

#pragma unroll 1
        for (int sub = 0; sub < CTILE / 32; ++sub) {
            const int cloc = sub * 32 + lane;
            const int cg   = cbase + cloc;
            const float4* rp = reinterpret_cast<const float4*>(&Cs[cloc * CPAD]);
            const float4 c0 = rp[0], c1 = rp[1], c2 = rp[2], c3 = rp[3];
            const float scv = Cs[cloc * CPAD + 16];

            float d2[QPW];
#pragma unroll
            for (int j = 0; j < QPW; ++j) {
                float a = 0.f;
                a = fmaf(qv[j][0],  c0.x, a); a = fmaf(qv[j][1],  c0.y, a);
                a = fmaf(qv[j][2],  c0.z, a); a = fmaf(qv[j][3],  c0.w, a);
                a = fmaf(qv[j][4],  c1.x, a); a = fmaf(qv[j][5],  c1.y, a);
                a = fmaf(qv[j][6],  c1.z, a); a = fmaf(qv[j][7],  c1.w, a);
                a = fmaf(qv[j][8],  c2.x, a); a = fmaf(qv[j][9],  c2.y, a);
                a = fmaf(qv[j][10], c2.z, a); a = fmaf(qv[j][11], c2.w, a);
                a = fmaf(qv[j][12], c3.x, a); a = fmaf(qv[j][13], c3.y, a);
                a = fmaf(qv[j][14], c3.z, a); a = fmaf(qv[j][15], c3.w, a);
                d2[j] = fmaf(-2.f, a, scv);
            }

            if (t == 0 && sub == 0) {
                // seed: lane k's candidate k -> list slot k (self -> FLTMAX hole)
#pragma unroll
                for (int j = 0; j < QPW; ++j) {
                    lv[j] = (lane < KNN && cg != qb + j) ? d2[j] : FLTMAX;
                    li[j] = cg;
                    maxreduce25(lv[j], lane, tau[j], mlane[j]);
                }
                unsigned pb = 0;
#pragma unroll
                for (int j = 0; j < QPW; ++j)
                    if (lane >= KNN && d2[j] < tau[j] && cg != qb + j) pb |= (1u << j);
#pragma unroll
                for (int j = 0; j < QPW; ++j) {
                    unsigned mask = __ballot_sync(FULLM, (pb >> j) & 1u);
                    while (mask) {
                        int src = __ffs(mask) - 1; mask &= mask - 1;
                        float dv = __shfl_sync(FULLM, d2[j], src);
                        int   ci = __shfl_sync(FULLM, cg, src);
                        if (dv < tau[j]) {
                            if (lane == mlane[j]) { lv[j] = dv; li[j] = ci; }
                            maxreduce25(lv[j], lane, tau[j], mlane[j]);
                        }
                    }
                }
                continue;
            }

            unsigned pb = 0;
#pragma unroll
            for (int j = 0; j < QPW; ++j)
                if (d2[j] < tau[j] && cg != qb + j) pb |= (1u << j);
            if (__ballot_sync(FULLM, pb)) {
#pragma unroll
                for (int j = 0; j < QPW; ++j) {
                    unsigned mask = __ballot_sync(FULLM, (pb >> j) & 1u);
                    while (mask) {
                        int src = __ffs(mask) - 1; mask &= mask - 1;
                        float dv = __shfl_sync(FULLM, d2[j], src);
                        int   ci = __shfl_sync(FULLM, cg, src);
                        if (dv < tau[j]) {
                            if (lane == mlane[j]) { lv[j] = dv; li[j] = ci; }
                            maxreduce25(lv[j], lane, tau[j], mlane[j]);
                        }
                    }
                }
            }
        }
    }

    if (lane < KNN) {
#pragma unroll
        for (int j = 0; j < QPW; ++j) g_nbrs[qb + j][lane] = li[j];
    }
}

// ---------------- kernel 4: per-point TSA term (warp per point) --------------
// P=1: sum((Pz-Px)^2) = 2 - 2*(u.v)^2, u,v unit top-eigenvectors.
// Eigvec by 7 repeated squarings (A^128), symmetric row-row matmul via
// LDS.128 on stride-20 rows; single mid-way max-diag rescale.
#define TSA_WPB 8
#define TSTR 20
__global__ void __launch_bounds__(256) k_tsa(const float* __restrict__ latent,
                                             const float* __restrict__ raw) {
    __shared__ float s_pts[TSA_WPB][KNN][ND];
    __shared__ float s_A[TSA_WPB][16 * TSTR];
    __shared__ float s_B[TSA_WPB][16 * TSTR];
    __shared__ float s_u[TSA_WPB][16];
    __shared__ float s_v[TSA_WPB][16];
    __shared__ float s_mu[TSA_WPB][16];
    __shared__ int   s_nb[TSA_WPB][KNN];

    const int w = threadIdx.x >> 5, lane = threadIdx.x & 31;
    const int i = blockIdx.x * TSA_WPB + w;
    const int ra   = lane >> 1;
    const int bpar = lane & 1;

    if (lane < KNN) s_nb[w][lane] = g_nbrs[i][lane];
    __syncwarp();

    for (int p = 0; p < 2; ++p) {
        const float* src = p ? raw : latent;
        float* uvec = p ? s_v[w] : s_u[w];

        for (int idx = lane; idx < KNN * ND; idx += 32) {
            int k = idx >> 4, d = idx & 15;
            s_pts[w][k][d] = src[(size_t)s_nb[w][k] * ND + d];
        }
        __syncwarp();
        if (lane < 16) {
            float m = 0.f;
#pragma unroll
            for (int k = 0; k < KNN; ++k) m += s_pts[w][k][lane];
            s_mu[w][lane] = m * (1.f / KNN);
        }
        __syncwarp();
        for (int idx = lane; idx < KNN * ND; idx += 32) {
            int k = idx >> 4, d = idx & 15;
            s_pts[w][k][d] -= s_mu[w][d];
        }
        __syncwarp();
        for (int e = lane; e < 256; e += 32) {
            int a = e >> 4, b = e & 15;
            float s = 0.f;
#pragma unroll
            for (int k = 0; k < KNN; ++k) s = fmaf(s_pts[w][k][a], s_pts[w][k][b], s);
            s_A[w][a * TSTR + b] = s;
        }
        __syncwarp();

        float* Ain = s_A[w];
        float* Aou = s_B[w];
#pragma unroll 1
        for (int sq = 0; sq < 7; ++sq) {
            const float4 A0 = *reinterpret_cast<const float4*>(Ain + ra * TSTR);
            const float4 A1 = *reinterpret_cast<const float4*>(Ain + ra * TSTR + 4);
            const float4 A2 = *reinterpret_cast<const float4*>(Ain + ra * TSTR + 8);
            const float4 A3 = *reinterpret_cast<const float4*>(Ain + ra * TSTR + 12);
#pragma unroll
            for (int ib = 0; ib < 8; ++ib) {
                const int b = bpar + 2 * ib;
                const float4 B0 = *reinterpret_cast<const float4*>(Ain + b * TSTR);
                const float4 B1 = *reinterpret_cast<const float4*>(Ain + b * TSTR + 4);
                const float4 B2 = *reinterpret_cast<const float4*>(Ain + b * TSTR + 8);
                const float4 B3 = *reinterpret_cast<const float4*>(Ain + b * TSTR + 12);
                float s = 0.f;
                s = fmaf(A0.x, B0.x, s); s = fmaf(A0.y, B0.y, s);
                s = fmaf(A0.z, B0.z, s); s = fmaf(A0.w, B0.w, s);
                s = fmaf(A1.x, B1.x, s); s = fmaf(A1.y, B1.y, s);
                s = fmaf(A1.z, B1.z, s); s = fmaf(A1.w, B1.w, s);
                s = fmaf(A2.x, B2.x, s); s = fmaf(A2.y, B2.y, s);
                s = fmaf(A2.z, B2.z, s); s = fmaf(A2.w, B2.w, s);
                s = fmaf(A3.x, B3.x, s); s = fmaf(A3.y, B3.y, s);
                s = fmaf(A3.z, B3.z, s); s = fmaf(A3.w, B3.w, s);
                Aou[ra * TSTR + b] = s;
            }
            __syncwarp();
            if (sq == 2) {
                float dv = (lane < 16) ? Aou[lane * TSTR + lane] : 0.f;
#pragma unroll
                for (int off = 16; off; off >>= 1)
                    dv = fmaxf(dv, __shfl_xor_sync(FULLM, dv, off));
                float inv = 1.f / fmaxf(dv, 1e-30f);
                for (int e = lane; e < 256; e += 32) {
                    int a = e >> 4, b = e & 15;
                    Aou[a * TSTR + b] *= inv;
                }
                __syncwarp();
            }
            float* tmp = Ain; Ain = Aou; Aou = tmp;
        }

        float bv = (lane < 16) ? Ain[lane * TSTR + lane] : -1.f;
        int   bx = (lane < 16) ? lane : 1000;
#pragma unroll
        for (int off = 16; off; off >>= 1) {
            float ov = __shfl_xor_sync(FULLM, bv, off);
            int   oi = __shfl_xor_sync(FULLM, bx, off);
            if (ov > bv || (ov == bv && oi < bx)) { bv = ov; bx = oi; }
        }
        float uv = (lane < 16) ? Ain[lane * TSTR + bx] : 0.f;
        float ss = uv * uv;
#pragma unroll
        for (int off = 16; off; off >>= 1) ss += __shfl_xor_sync(FULLM, ss, off);
        float rn = rsqrtf(ss);
        if (lane < 16) uvec[lane] = uv * rn;
        __syncwarp();
    }

    float pd = (lane < 16) ? s_u[w][lane] * s_v[w][lane] : 0.f;
#pragma unroll
    for (int off = 16; off; off >>= 1) pd += __shfl_xor_sync(FULLM, pd, off);
    if (lane == 0) {
        float term = fmaf(-2.f * pd, pd, 2.f);
        atomicAdd(&g_acc_tsa, term);
    }
}

// ---------------- kernel 5: finalize ----------------
__global__ void k_final(float* __restrict__ out) {
    out[0] = g_acc_recon * (1.f / (NB * ND)) + LAMBDA_TSA * g_acc_tsa * (1.f / NB);
}

// ---------------- launcher (kernel launches only; graph-capturable) ----------
extern "C" void kernel_launch(void* const* d_in, const int* in_sizes, int n_in,
                              void* d_out, int out_size) {
    const float* outputs = (const float*)d_in[0];
    const float* targets = (const float*)d_in[1];
    const float* latent  = (const float*)d_in[2];
    const float* raw     = (const float*)d_in[3];
    float* out = (float*)d_out;

    k_setup<<<NB / 256, 256>>>(raw);
    k_recon<<<64, 256>>>(outputs, targets);
    k_dummy<<<1, 1>>>();                      // slot 3: ncu captures k_knn
    k_knn<<<NB / QPB, 256>>>(raw);
    k_tsa<<<NB / TSA_WPB, 256>>>(latent, raw);
    k_final<<<1, 1>>>(out);
}